// round 1
// baseline (speedup 1.0000x reference)
#include <cuda_runtime.h>
#include <math.h>

#define EMBED    256
#define HEADS    8
#define LEVELS   4
#define POINTS   4
#define HEAD_DIM 32
#define NQ       20000
#define NB       2
#define HP       128
#define WP       128
#define NVAL     (NB*HP*WP*LEVELS)   // 131072 rows for value projection

// ---------------- device scratch (static, no allocations) ----------------
__device__ float g_xn  [NQ*EMBED];                       // layernorm output
__device__ float g_xq  [NQ*EMBED];                       // q_in_proj output
__device__ float g_off [NQ*EMBED];                       // offsets (H*L*P*2 = 256)
__device__ float g_attn[NQ*HEADS*LEVELS*POINTS];         // attn logits (128/query)
__device__ float g_val [(size_t)NVAL*EMBED];             // projected value, 134MB
__device__ float g_samp[NQ*EMBED];                       // sampled/attended output

// ---------------- LayerNorm: one warp per query row ----------------
__global__ void ln_kernel(const float* __restrict__ q,
                          const float* __restrict__ gamma,
                          const float* __restrict__ beta,
                          float* __restrict__ out)
{
    int warp = (blockIdx.x * blockDim.x + threadIdx.x) >> 5;
    int lane = threadIdx.x & 31;
    if (warp >= NQ) return;
    const float* row = q + (size_t)warp * EMBED;
    float v[8];
    float sum = 0.f;
#pragma unroll
    for (int i = 0; i < 8; i++) { v[i] = row[lane + i*32]; sum += v[i]; }
#pragma unroll
    for (int o = 16; o; o >>= 1) sum += __shfl_xor_sync(0xffffffffu, sum, o);
    float mean = sum * (1.0f/EMBED);
    float var = 0.f;
#pragma unroll
    for (int i = 0; i < 8; i++) { float d = v[i]-mean; var += d*d; }
#pragma unroll
    for (int o = 16; o; o >>= 1) var += __shfl_xor_sync(0xffffffffu, var, o);
    var *= (1.0f/EMBED);
    float inv = rsqrtf(var + 1e-5f);
    float* orow = out + (size_t)warp * EMBED;
#pragma unroll
    for (int i = 0; i < 8; i++) {
        int c = lane + i*32;
        orow[c] = (v[i]-mean)*inv*gamma[c] + beta[c];
    }
}

// ---------------- classic 128x128x8 SGEMM, optional bias + residual ----------------
// C[M,N] = A[M,K] @ B[K,N] (+ bias[N]) (+ Cadd[M,N])
__global__ __launch_bounds__(256)
void sgemm_kernel(const float* __restrict__ A, const float* __restrict__ B,
                  const float* __restrict__ bias, const float* __restrict__ Cadd,
                  float* __restrict__ C, int M, int N, int K)
{
    __shared__ float As[8][128];
    __shared__ float Bs[8][128];

    int tid = threadIdx.x;
    int rowBase = blockIdx.y * 128;
    int colBase = blockIdx.x * 128;

    int ty = tid >> 4;      // 0..15
    int tx = tid & 15;      // 0..15

    float acc[8][8];
#pragma unroll
    for (int i = 0; i < 8; i++)
#pragma unroll
        for (int j = 0; j < 8; j++) acc[i][j] = 0.f;

    int aRow = tid >> 1;           // 0..127
    int aCol = (tid & 1) * 4;      // 0 or 4
    int bRow = tid >> 5;           // 0..7
    int bCol = (tid & 31) * 4;     // 0..124

    for (int k0 = 0; k0 < K; k0 += 8) {
        float4 av;
        int gr = rowBase + aRow;
        if (gr < M) av = *(const float4*)(A + (size_t)gr*K + k0 + aCol);
        else        av = make_float4(0.f,0.f,0.f,0.f);
        As[aCol+0][aRow] = av.x;
        As[aCol+1][aRow] = av.y;
        As[aCol+2][aRow] = av.z;
        As[aCol+3][aRow] = av.w;

        float4 bv = *(const float4*)(B + (size_t)(k0+bRow)*N + colBase + bCol);
        *(float4*)&Bs[bRow][bCol] = bv;
        __syncthreads();

#pragma unroll
        for (int k = 0; k < 8; k++) {
            float4 a0 = *(const float4*)&As[k][ty*8];
            float4 a1 = *(const float4*)&As[k][ty*8+4];
            float4 b0 = *(const float4*)&Bs[k][tx*8];
            float4 b1 = *(const float4*)&Bs[k][tx*8+4];
            float ra[8] = {a0.x,a0.y,a0.z,a0.w,a1.x,a1.y,a1.z,a1.w};
            float rb[8] = {b0.x,b0.y,b0.z,b0.w,b1.x,b1.y,b1.z,b1.w};
#pragma unroll
            for (int i = 0; i < 8; i++)
#pragma unroll
                for (int j = 0; j < 8; j++) acc[i][j] += ra[i]*rb[j];
        }
        __syncthreads();
    }

#pragma unroll
    for (int i = 0; i < 8; i++) {
        int r = rowBase + ty*8 + i;
        if (r >= M) continue;
#pragma unroll
        for (int j = 0; j < 8; j += 4) {
            int c = colBase + tx*8 + j;
            float4 v = make_float4(acc[i][j], acc[i][j+1], acc[i][j+2], acc[i][j+3]);
            if (bias) {
                v.x += bias[c];   v.y += bias[c+1];
                v.z += bias[c+2]; v.w += bias[c+3];
            }
            if (Cadd) {
                float4 rr = *(const float4*)(Cadd + (size_t)r*N + c);
                v.x += rr.x; v.y += rr.y; v.z += rr.z; v.w += rr.w;
            }
            *(float4*)(C + (size_t)r*N + c) = v;
        }
    }
}

// ---------------- sampling: one block per query, one warp per head ----------------
__global__ __launch_bounds__(256)
void sample_kernel(const float* __restrict__ pos,
                   const int*   __restrict__ boff,
                   const int*   __restrict__ lshapes)
{
    int q    = blockIdx.x;
    int h    = threadIdx.x >> 5;
    int lane = threadIdx.x & 31;

    int b = (q >= boff[1]) ? 1 : 0;

    float posy = pos[q*2+0];
    float posx = pos[q*2+1];

    int   Hi[LEVELS], Wi[LEVELS];
    float Hf[LEVELS], Wf[LEVELS];
#pragma unroll
    for (int l = 0; l < LEVELS; l++) {
        Hi[l] = lshapes[l*2+0]; Wi[l] = lshapes[l*2+1];
        Hf[l] = (float)Hi[l];   Wf[l] = (float)Wi[l];
    }

    // softmax over 16 logits for this (q,h); lanes 0..15 hold points
    const float* alog = g_attn + (size_t)q*(HEADS*LEVELS*POINTS) + h*(LEVELS*POINTS);
    float logit = (lane < 16) ? alog[lane] : -1e30f;
    float mx = logit;
#pragma unroll
    for (int o = 8; o; o >>= 1) mx = fmaxf(mx, __shfl_xor_sync(0xffffffffu, mx, o));
    float e = (lane < 16) ? expf(logit - mx) : 0.f;
    float s = e;
#pragma unroll
    for (int o = 8; o; o >>= 1) s += __shfl_xor_sync(0xffffffffu, s, o);
    float aw = e / s;

    const float* offrow = g_off + (size_t)q*EMBED + h*(LEVELS*POINTS*2);

    float acc = 0.f;
#pragma unroll
    for (int lp = 0; lp < LEVELS*POINTS; lp++) {
        int l = lp >> 2;
        float a  = __shfl_sync(0xffffffffu, aw, lp);
        float oy = offrow[lp*2+0];
        float ox = offrow[lp*2+1];
        float hf = Hf[l], wf = Wf[l];
        // replicate reference arithmetic: pix = (pos + off/shp)*shp - 0.5
        float py = (posy + oy/hf)*hf - 0.5f;
        float px = (posx + ox/wf)*wf - 0.5f;
        float y0f = floorf(py), x0f = floorf(px);
        float wy = py - y0f,    wx = px - x0f;
        int y0 = (int)y0f, x0 = (int)x0f;
        int Hl = Hi[l],    Wl = Wi[l];

#pragma unroll
        for (int c = 0; c < 4; c++) {
            int yi = y0 + (c >> 1);
            int xi = x0 + (c & 1);
            float w = ((c >> 1) ? wy : (1.f-wy)) * ((c & 1) ? wx : (1.f-wx));
            if (yi >= 0 && yi < Hl && xi >= 0 && xi < Wl) {
                size_t idx = ((((((size_t)b*HP + yi)*WP + xi)*LEVELS + l)*HEADS + h)
                              * HEAD_DIM) + lane;
                acc += a * w * g_val[idx];
            }
        }
    }
    g_samp[(size_t)q*EMBED + h*HEAD_DIM + lane] = acc;
}

// ---------------- launcher ----------------
extern "C" void kernel_launch(void* const* d_in, const int* in_sizes, int n_in,
                              void* d_out, int out_size)
{
    const float* query   = (const float*)d_in[0];
    const float* qpos    = (const float*)d_in[1];
    const int*   qboff   = (const int*)  d_in[2];
    const float* fmaps   = (const float*)d_in[3];
    const int*   lshapes = (const int*)  d_in[4];
    const float* gamma   = (const float*)d_in[5];
    const float* beta    = (const float*)d_in[6];
    const float* W_q     = (const float*)d_in[7];
    const float* W_off   = (const float*)d_in[8];
    const float* b_off   = (const float*)d_in[9];
    const float* W_attn  = (const float*)d_in[10];
    const float* b_attn  = (const float*)d_in[11];
    const float* W_val   = (const float*)d_in[12];
    const float* b_val   = (const float*)d_in[13];
    const float* W_out   = (const float*)d_in[14];
    float* out = (float*)d_out;

    float *xn, *xq, *off, *attn, *val, *samp;
    cudaGetSymbolAddress((void**)&xn,   g_xn);
    cudaGetSymbolAddress((void**)&xq,   g_xq);
    cudaGetSymbolAddress((void**)&off,  g_off);
    cudaGetSymbolAddress((void**)&attn, g_attn);
    cudaGetSymbolAddress((void**)&val,  g_val);
    cudaGetSymbolAddress((void**)&samp, g_samp);

    // 1) LayerNorm
    {
        int warps = NQ;
        int threads = 256;
        int blocks = (warps*32 + threads - 1) / threads;
        ln_kernel<<<blocks, threads>>>(query, gamma, beta, xn);
    }

    // 2) xq = xn @ W_q   [20000,256]
    {
        dim3 grid(EMBED/128, (NQ + 127)/128);
        sgemm_kernel<<<grid, 256>>>(xn, W_q, nullptr, nullptr, xq, NQ, EMBED, EMBED);
    }

    // 3) off = xq @ W_off + b_off   [20000,256]
    {
        dim3 grid(EMBED/128, (NQ + 127)/128);
        sgemm_kernel<<<grid, 256>>>(xq, W_off, b_off, nullptr, off, NQ, EMBED, EMBED);
    }

    // 4) attn logits = xq @ W_attn + b_attn   [20000,128]
    {
        dim3 grid(1, (NQ + 127)/128);
        sgemm_kernel<<<grid, 256>>>(xq, W_attn, b_attn, nullptr, attn, NQ, 128, EMBED);
    }

    // 5) value = fmaps @ W_val + b_val   [131072,256]  (dominant GEMM)
    {
        dim3 grid(EMBED/128, NVAL/128);
        sgemm_kernel<<<grid, 256>>>(fmaps, W_val, b_val, nullptr, val, NVAL, EMBED, EMBED);
    }

    // 6) softmax + bilinear sampling + head-weighted sum -> g_samp [20000,256]
    {
        sample_kernel<<<NQ, 256>>>(qpos, qboff, lshapes);
    }

    // 7) out = g_samp @ W_out + residual(query)
    {
        dim3 grid(EMBED/128, (NQ + 127)/128);
        sgemm_kernel<<<grid, 256>>>(samp, W_out, nullptr, query, out, NQ, EMBED, EMBED);
    }
}

// round 3
// speedup vs baseline: 1.5508x; 1.5508x over previous
#include <cuda_runtime.h>
#include <cuda_bf16.h>
#include <math.h>
#include <stdint.h>

#define EMBED    256
#define HEADS    8
#define LEVELS   4
#define POINTS   4
#define HEAD_DIM 32
#define NQ       20000
#define NB       2
#define HP       128
#define WP       128
#define NVAL     (NB*HP*WP*LEVELS)   // 131072
#define KDIM     256

// ---------------- device scratch (static, no allocations) ----------------
__device__ float g_xn  [NQ*EMBED];
__device__ float g_xq  [NQ*EMBED];
__device__ float g_off [NQ*EMBED];
__device__ float g_attn[NQ*HEADS*LEVELS*POINTS];
__device__ float g_val [(size_t)NVAL*EMBED];
__device__ float g_samp[NQ*EMBED];
__device__ float g_wt  [5*65536];   // transposed weights (K-major [N,K])

// ---------------- helpers ----------------
__device__ __forceinline__ uint32_t smem_u32(const void* p) {
    uint32_t a;
    asm("{ .reg .u64 t; cvta.to.shared.u64 t, %1; cvt.u32.u64 %0, t; }" : "=r"(a) : "l"(p));
    return a;
}
__device__ __forceinline__ void ldm_x4(uint32_t* r, uint32_t addr) {
    asm volatile("ldmatrix.sync.aligned.m8n8.x4.shared.b16 {%0,%1,%2,%3}, [%4];"
                 : "=r"(r[0]), "=r"(r[1]), "=r"(r[2]), "=r"(r[3]) : "r"(addr));
}
__device__ __forceinline__ void mma_bf16(float* c, const uint32_t* a, const uint32_t* b) {
    asm volatile("mma.sync.aligned.m16n8k16.row.col.f32.bf16.bf16.f32 "
                 "{%0,%1,%2,%3},{%4,%5,%6,%7},{%8,%9},{%0,%1,%2,%3};"
                 : "+f"(c[0]), "+f"(c[1]), "+f"(c[2]), "+f"(c[3])
                 : "r"(a[0]), "r"(a[1]), "r"(a[2]), "r"(a[3]), "r"(b[0]), "r"(b[1]));
}
__device__ __forceinline__ uint32_t pack_bf16(float a, float b) {
    __nv_bfloat162 p = __floats2bfloat162_rn(a, b);
    return *(uint32_t*)&p;
}

// ---------------- weight transpose: src[256,N] -> dst[N,256] ----------------
__global__ void transpose_k(const float* __restrict__ src, float* __restrict__ dst, int N)
{
    __shared__ float t[32][33];
    int bx = blockIdx.x * 32;   // over N
    int by = blockIdx.y * 32;   // over K=256
#pragma unroll
    for (int i = 0; i < 4; i++) {
        int y = by + threadIdx.y + i*8;
        t[threadIdx.y + i*8][threadIdx.x] = src[(size_t)y*N + bx + threadIdx.x];
    }
    __syncthreads();
#pragma unroll
    for (int i = 0; i < 4; i++) {
        int yo = bx + threadIdx.y + i*8;
        dst[(size_t)yo*256 + by + threadIdx.x] = t[threadIdx.x][threadIdx.y + i*8];
    }
}

// ---------------- bf16x3 mma.sync GEMM ----------------
// C[M,Nglob] = A[M,256] @ Bt[Nglob,256]^T (+bias) (+Cadd)
// Block 128x128x(K=256, chunks of 32). 8 warps, each 64(m) x 32(n).
#define LDA 40   // smem row pitch in halves (padded)
__global__ __launch_bounds__(256)
void mma_gemm(const float* __restrict__ A, const float* __restrict__ Bt,
              const float* __restrict__ bias, const float* __restrict__ Cadd,
              float* __restrict__ C, int M, int Nglob)
{
    __shared__ __align__(16) uint16_t Ah[128*LDA];
    __shared__ __align__(16) uint16_t Al[128*LDA];
    __shared__ __align__(16) uint16_t Bh[128*LDA];
    __shared__ __align__(16) uint16_t Bl[128*LDA];

    const int tid  = threadIdx.x;
    const int wid  = tid >> 5;
    const int lane = tid & 31;
    const int warpM = wid & 1;        // 0..1  (64 rows each)
    const int warpN = wid >> 1;       // 0..3  (32 cols each)
    const int rowBase = blockIdx.y * 128;
    const int colBase = blockIdx.x * 128;

    const uint32_t sAh = smem_u32(Ah), sAl = smem_u32(Al);
    const uint32_t sBh = smem_u32(Bh), sBl = smem_u32(Bl);

    float acc[4][4][4];
#pragma unroll
    for (int i = 0; i < 4; i++)
#pragma unroll
        for (int j = 0; j < 4; j++)
#pragma unroll
            for (int k = 0; k < 4; k++) acc[i][j][k] = 0.f;

    // ldmatrix per-thread source addresses (byte offsets within tile)
    // A (and B) x4: t<16 -> row mbase+t, kcol kbase; t>=16 -> row mbase+(t-16), kcol kbase+8
    const int a_row_off = lane & 15;
    const int a_k_off   = (lane >> 4) * 8;
    // B x4 (two n-tiles): row = nbase + (t%8) + (t/16)*8 ; kcol = kbase + ((t>>3)&1)*8
    const int b_row_off = (lane & 7) + ((lane >> 4) << 3);
    const int b_k_off   = ((lane >> 3) & 1) * 8;

    for (int c = 0; c < KDIM/32; c++) {
        __syncthreads();
        // ---- load + convert A tile: 128 rows x 32 floats ----
#pragma unroll
        for (int j = 0; j < 4; j++) {
            int i = tid + 256*j;
            int row = i >> 3, c4 = i & 7;
            int gr = rowBase + row;
            float4 v = make_float4(0.f, 0.f, 0.f, 0.f);
            if (gr < M) v = *(const float4*)(A + (size_t)gr*KDIM + c*32 + c4*4);
            __nv_bfloat16 h0 = __float2bfloat16(v.x);
            __nv_bfloat16 h1 = __float2bfloat16(v.y);
            __nv_bfloat16 h2 = __float2bfloat16(v.z);
            __nv_bfloat16 h3 = __float2bfloat16(v.w);
            uint2 hh, ll;
            hh.x = pack_bf16(__bfloat162float(h0), __bfloat162float(h1));
            hh.y = pack_bf16(__bfloat162float(h2), __bfloat162float(h3));
            ll.x = pack_bf16(v.x - __bfloat162float(h0), v.y - __bfloat162float(h1));
            ll.y = pack_bf16(v.z - __bfloat162float(h2), v.w - __bfloat162float(h3));
            *(uint2*)&Ah[row*LDA + c4*4] = hh;
            *(uint2*)&Al[row*LDA + c4*4] = ll;
        }
        // ---- load + convert B tile: 128 n-rows x 32 floats ----
#pragma unroll
        for (int j = 0; j < 4; j++) {
            int i = tid + 256*j;
            int row = i >> 3, c4 = i & 7;
            float4 v = *(const float4*)(Bt + (size_t)(colBase + row)*KDIM + c*32 + c4*4);
            __nv_bfloat16 h0 = __float2bfloat16(v.x);
            __nv_bfloat16 h1 = __float2bfloat16(v.y);
            __nv_bfloat16 h2 = __float2bfloat16(v.z);
            __nv_bfloat16 h3 = __float2bfloat16(v.w);
            uint2 hh, ll;
            hh.x = pack_bf16(__bfloat162float(h0), __bfloat162float(h1));
            hh.y = pack_bf16(__bfloat162float(h2), __bfloat162float(h3));
            ll.x = pack_bf16(v.x - __bfloat162float(h0), v.y - __bfloat162float(h1));
            ll.y = pack_bf16(v.z - __bfloat162float(h2), v.w - __bfloat162float(h3));
            *(uint2*)&Bh[row*LDA + c4*4] = hh;
            *(uint2*)&Bl[row*LDA + c4*4] = ll;
        }
        __syncthreads();

        // ---- 2 k16 steps x 3 terms ----
#pragma unroll
        for (int ks = 0; ks < 2; ks++) {
            const int kb = ks * 16;
            uint32_t ah[4][4], al[4][4], bh[2][4], bl[2][4];
#pragma unroll
            for (int mt = 0; mt < 4; mt++) {
                int row = warpM*64 + mt*16 + a_row_off;
                uint32_t off = (uint32_t)(row*LDA + kb + a_k_off) * 2;
                ldm_x4(ah[mt], sAh + off);
                ldm_x4(al[mt], sAl + off);
            }
#pragma unroll
            for (int np = 0; np < 2; np++) {
                int row = warpN*32 + np*16 + b_row_off;
                uint32_t off = (uint32_t)(row*LDA + kb + b_k_off) * 2;
                ldm_x4(bh[np], sBh + off);
                ldm_x4(bl[np], sBl + off);
            }
#pragma unroll
            for (int mt = 0; mt < 4; mt++)
#pragma unroll
                for (int nt = 0; nt < 4; nt++) {
                    const uint32_t* Bhp = &bh[nt>>1][(nt&1)*2];
                    const uint32_t* Blp = &bl[nt>>1][(nt&1)*2];
                    mma_bf16(acc[mt][nt], ah[mt], Bhp);
                    mma_bf16(acc[mt][nt], al[mt], Bhp);
                    mma_bf16(acc[mt][nt], ah[mt], Blp);
                }
        }
    }

    // ---- epilogue ----
    const int g   = lane >> 2;
    const int tig = lane & 3;
#pragma unroll
    for (int mt = 0; mt < 4; mt++) {
        int r0 = rowBase + warpM*64 + mt*16 + g;
        int r1 = r0 + 8;
#pragma unroll
        for (int nt = 0; nt < 4; nt++) {
            int col = colBase + warpN*32 + nt*8 + tig*2;
            float2 v0 = make_float2(acc[mt][nt][0], acc[mt][nt][1]);
            float2 v1 = make_float2(acc[mt][nt][2], acc[mt][nt][3]);
            if (bias) {
                float b0 = bias[col], b1 = bias[col+1];
                v0.x += b0; v0.y += b1;
                v1.x += b0; v1.y += b1;
            }
            if (r0 < M) {
                if (Cadd) {
                    float2 rr = *(const float2*)(Cadd + (size_t)r0*Nglob + col);
                    v0.x += rr.x; v0.y += rr.y;
                }
                *(float2*)(C + (size_t)r0*Nglob + col) = v0;
            }
            if (r1 < M) {
                if (Cadd) {
                    float2 rr = *(const float2*)(Cadd + (size_t)r1*Nglob + col);
                    v1.x += rr.x; v1.y += rr.y;
                }
                *(float2*)(C + (size_t)r1*Nglob + col) = v1;
            }
        }
    }
}

// ---------------- LayerNorm: one warp per query row ----------------
__global__ void ln_kernel(const float* __restrict__ q,
                          const float* __restrict__ gamma,
                          const float* __restrict__ beta,
                          float* __restrict__ out)
{
    int warp = (blockIdx.x * blockDim.x + threadIdx.x) >> 5;
    int lane = threadIdx.x & 31;
    if (warp >= NQ) return;
    const float* row = q + (size_t)warp * EMBED;
    float v[8];
    float sum = 0.f;
#pragma unroll
    for (int i = 0; i < 8; i++) { v[i] = row[lane + i*32]; sum += v[i]; }
#pragma unroll
    for (int o = 16; o; o >>= 1) sum += __shfl_xor_sync(0xffffffffu, sum, o);
    float mean = sum * (1.0f/EMBED);
    float var = 0.f;
#pragma unroll
    for (int i = 0; i < 8; i++) { float d = v[i]-mean; var += d*d; }
#pragma unroll
    for (int o = 16; o; o >>= 1) var += __shfl_xor_sync(0xffffffffu, var, o);
    var *= (1.0f/EMBED);
    float inv = rsqrtf(var + 1e-5f);
    float* orow = out + (size_t)warp * EMBED;
#pragma unroll
    for (int i = 0; i < 8; i++) {
        int c = lane + i*32;
        orow[c] = (v[i]-mean)*inv*gamma[c] + beta[c];
    }
}

// ---------------- sampling: one block per query, one warp per head ----------------
__global__ __launch_bounds__(256)
void sample_kernel(const float* __restrict__ pos,
                   const int*   __restrict__ boff,
                   const int*   __restrict__ lshapes)
{
    int q    = blockIdx.x;
    int h    = threadIdx.x >> 5;
    int lane = threadIdx.x & 31;

    int b = (q >= boff[1]) ? 1 : 0;

    float posy = pos[q*2+0];
    float posx = pos[q*2+1];

    int   Hi[LEVELS], Wi[LEVELS];
    float Hf[LEVELS], Wf[LEVELS];
#pragma unroll
    for (int l = 0; l < LEVELS; l++) {
        Hi[l] = lshapes[l*2+0]; Wi[l] = lshapes[l*2+1];
        Hf[l] = (float)Hi[l];   Wf[l] = (float)Wi[l];
    }

    const float* alog = g_attn + (size_t)q*(HEADS*LEVELS*POINTS) + h*(LEVELS*POINTS);
    float logit = (lane < 16) ? alog[lane] : -1e30f;
    float mx = logit;
#pragma unroll
    for (int o = 8; o; o >>= 1) mx = fmaxf(mx, __shfl_xor_sync(0xffffffffu, mx, o));
    float e = (lane < 16) ? expf(logit - mx) : 0.f;
    float s = e;
#pragma unroll
    for (int o = 8; o; o >>= 1) s += __shfl_xor_sync(0xffffffffu, s, o);
    float aw = e / s;

    const float* offrow = g_off + (size_t)q*EMBED + h*(LEVELS*POINTS*2);

    float acc = 0.f;
#pragma unroll
    for (int lp = 0; lp < LEVELS*POINTS; lp++) {
        int l = lp >> 2;
        float a  = __shfl_sync(0xffffffffu, aw, lp);
        float oy = offrow[lp*2+0];
        float ox = offrow[lp*2+1];
        float hf = Hf[l], wf = Wf[l];
        float py = (posy + oy/hf)*hf - 0.5f;
        float px = (posx + ox/wf)*wf - 0.5f;
        float y0f = floorf(py), x0f = floorf(px);
        float wy = py - y0f,    wx = px - x0f;
        int y0 = (int)y0f, x0 = (int)x0f;
        int Hl = Hi[l],    Wl = Wi[l];

#pragma unroll
        for (int cc = 0; cc < 4; cc++) {
            int yi = y0 + (cc >> 1);
            int xi = x0 + (cc & 1);
            float w = ((cc >> 1) ? wy : (1.f-wy)) * ((cc & 1) ? wx : (1.f-wx));
            if (yi >= 0 && yi < Hl && xi >= 0 && xi < Wl) {
                size_t idx = ((((((size_t)b*HP + yi)*WP + xi)*LEVELS + l)*HEADS + h)
                              * HEAD_DIM) + lane;
                acc += a * w * g_val[idx];
            }
        }
    }
    g_samp[(size_t)q*EMBED + h*HEAD_DIM + lane] = acc;
}

// ---------------- launcher ----------------
extern "C" void kernel_launch(void* const* d_in, const int* in_sizes, int n_in,
                              void* d_out, int out_size)
{
    const float* query   = (const float*)d_in[0];
    const float* qpos    = (const float*)d_in[1];
    const int*   qboff   = (const int*)  d_in[2];
    const float* fmaps   = (const float*)d_in[3];
    const int*   lshapes = (const int*)  d_in[4];
    const float* gamma   = (const float*)d_in[5];
    const float* beta    = (const float*)d_in[6];
    const float* W_q     = (const float*)d_in[7];
    const float* W_off   = (const float*)d_in[8];
    const float* b_off   = (const float*)d_in[9];
    const float* W_attn  = (const float*)d_in[10];
    const float* b_attn  = (const float*)d_in[11];
    const float* W_val   = (const float*)d_in[12];
    const float* b_val   = (const float*)d_in[13];
    const float* W_out   = (const float*)d_in[14];
    float* out = (float*)d_out;

    float *xn, *xq, *off, *attn, *val, *samp, *wt;
    cudaGetSymbolAddress((void**)&xn,   g_xn);
    cudaGetSymbolAddress((void**)&xq,   g_xq);
    cudaGetSymbolAddress((void**)&off,  g_off);
    cudaGetSymbolAddress((void**)&attn, g_attn);
    cudaGetSymbolAddress((void**)&val,  g_val);
    cudaGetSymbolAddress((void**)&samp, g_samp);
    cudaGetSymbolAddress((void**)&wt,   g_wt);

    float* wq_t    = wt;
    float* woff_t  = wt + 65536;
    float* wval_t  = wt + 131072;
    float* wout_t  = wt + 196608;
    float* wattn_t = wt + 262144;

    // 0) transpose weights to K-major [N, K]
    {
        dim3 blk(32, 8);
        transpose_k<<<dim3(8, 8), blk>>>(W_q,    wq_t,    256);
        transpose_k<<<dim3(8, 8), blk>>>(W_off,  woff_t,  256);
        transpose_k<<<dim3(4, 8), blk>>>(W_attn, wattn_t, 128);
        transpose_k<<<dim3(8, 8), blk>>>(W_val,  wval_t,  256);
        transpose_k<<<dim3(8, 8), blk>>>(W_out,  wout_t,  256);
    }

    // 1) LayerNorm
    ln_kernel<<<(NQ*32 + 255)/256, 256>>>(query, gamma, beta, xn);

    const int MQT = (NQ + 127) / 128;  // 157

    // 2) xq = xn @ W_q
    mma_gemm<<<dim3(2, MQT), 256>>>(xn, wq_t, nullptr, nullptr, xq, NQ, 256);

    // 3) off = xq @ W_off + b_off
    mma_gemm<<<dim3(2, MQT), 256>>>(xq, woff_t, b_off, nullptr, off, NQ, 256);

    // 4) attn logits = xq @ W_attn + b_attn
    mma_gemm<<<dim3(1, MQT), 256>>>(xq, wattn_t, b_attn, nullptr, attn, NQ, 128);

    // 5) value = fmaps @ W_val + b_val   (dominant GEMM)
    mma_gemm<<<dim3(2, NVAL/128), 256>>>(fmaps, wval_t, b_val, nullptr, val, NVAL, 256);

    // 6) softmax + bilinear sampling
    sample_kernel<<<NQ, 256>>>(qpos, qboff, lshapes);

    // 7) out = samp @ W_out + residual
    mma_gemm<<<dim3(2, MQT), 256>>>(samp, wout_t, nullptr, query, out, NQ, 256);
}

// round 4
// speedup vs baseline: 1.5782x; 1.0177x over previous
#include <cuda_runtime.h>
#include <cuda_bf16.h>
#include <cuda_fp16.h>
#include <math.h>
#include <stdint.h>

#define EMBED    256
#define HEADS    8
#define LEVELS   4
#define POINTS   4
#define HEAD_DIM 32
#define NQ       20000
#define NB       2
#define HP       128
#define WP       128
#define NVAL     (NB*HP*WP*LEVELS)   // 131072
#define KDIM     256

// ---------------- device scratch (static, no allocations) ----------------
__device__ float  g_xn  [NQ*EMBED];
__device__ float  g_xq  [NQ*EMBED];
__device__ float  g_ofat[NQ*384];                 // fused [off(256) | attn(128)]
__device__ __half g_val [(size_t)NVAL*EMBED];     // projected value, fp16, 67MB
__device__ float  g_samp[NQ*EMBED];
// transposed + bf16-split weights, K-major [N,256]:
// wq:0..65535  wofat:65536..163839  wval:163840..229375  wout:229376..294911
__device__ __nv_bfloat16 g_wth[294912];
__device__ __nv_bfloat16 g_wtl[294912];
__device__ float g_bofat[384];

// ---------------- helpers ----------------
__device__ __forceinline__ uint32_t smem_u32(const void* p) {
    uint32_t a;
    asm("{ .reg .u64 t; cvta.to.shared.u64 t, %1; cvt.u32.u64 %0, t; }" : "=r"(a) : "l"(p));
    return a;
}
__device__ __forceinline__ void ldm_x4(uint32_t* r, uint32_t addr) {
    asm volatile("ldmatrix.sync.aligned.m8n8.x4.shared.b16 {%0,%1,%2,%3}, [%4];"
                 : "=r"(r[0]), "=r"(r[1]), "=r"(r[2]), "=r"(r[3]) : "r"(addr));
}
__device__ __forceinline__ void mma_bf16(float* c, const uint32_t* a, const uint32_t* b) {
    asm volatile("mma.sync.aligned.m16n8k16.row.col.f32.bf16.bf16.f32 "
                 "{%0,%1,%2,%3},{%4,%5,%6,%7},{%8,%9},{%0,%1,%2,%3};"
                 : "+f"(c[0]), "+f"(c[1]), "+f"(c[2]), "+f"(c[3])
                 : "r"(a[0]), "r"(a[1]), "r"(a[2]), "r"(a[3]), "r"(b[0]), "r"(b[1]));
}
__device__ __forceinline__ uint32_t pack_bf16(float a, float b) {
    __nv_bfloat162 p = __floats2bfloat162_rn(a, b);
    return *(uint32_t*)&p;
}

// ---------------- transpose + bf16 hi/lo split: src[256,N] -> dst[N,256] ----------------
__global__ void transpose_split(const float* __restrict__ src,
                                __nv_bfloat16* __restrict__ dh,
                                __nv_bfloat16* __restrict__ dl, int N)
{
    __shared__ float t[32][33];
    int bx = blockIdx.x * 32;   // over N
    int by = blockIdx.y * 32;   // over K=256
#pragma unroll
    for (int i = 0; i < 4; i++) {
        int y = by + threadIdx.y + i*8;
        t[threadIdx.y + i*8][threadIdx.x] = src[(size_t)y*N + bx + threadIdx.x];
    }
    __syncthreads();
#pragma unroll
    for (int i = 0; i < 4; i++) {
        int row = bx + threadIdx.y + i*8;
        float v = t[threadIdx.x][threadIdx.y + i*8];
        __nv_bfloat16 h = __float2bfloat16(v);
        dh[(size_t)row*256 + by + threadIdx.x] = h;
        dl[(size_t)row*256 + by + threadIdx.x] = __float2bfloat16(v - __bfloat162float(h));
    }
}

__global__ void bias_concat(const float* __restrict__ b_off, const float* __restrict__ b_attn)
{
    int i = threadIdx.x + blockIdx.x*blockDim.x;
    if (i < 384) g_bofat[i] = (i < 256) ? b_off[i] : b_attn[i-256];
}

// ---------------- bf16x3 mma.sync GEMM ----------------
// C[M,Nglob] = A[M,256] @ Bt[Nglob,256]^T (+bias) (+Cadd). Bt pre-split bf16 hi/lo.
// Block 128x128x(K chunks of 32). 8 warps, each 64(m) x 32(n).
#define LDA 40
template<typename OT>
__global__ __launch_bounds__(256)
void mma_gemm(const float* __restrict__ A,
              const __nv_bfloat16* __restrict__ Bth,
              const __nv_bfloat16* __restrict__ Btl,
              const float* __restrict__ bias, const float* __restrict__ Cadd,
              OT* __restrict__ C, int M, int Nglob)
{
    __shared__ __align__(16) uint16_t Ah[128*LDA];
    __shared__ __align__(16) uint16_t Al[128*LDA];
    __shared__ __align__(16) uint16_t Bh[128*LDA];
    __shared__ __align__(16) uint16_t Bl[128*LDA];

    const int tid  = threadIdx.x;
    const int wid  = tid >> 5;
    const int lane = tid & 31;
    const int warpM = wid & 1;
    const int warpN = wid >> 1;
    const int rowBase = blockIdx.y * 128;
    const int colBase = blockIdx.x * 128;

    const uint32_t sAh = smem_u32(Ah), sAl = smem_u32(Al);
    const uint32_t sBh = smem_u32(Bh), sBl = smem_u32(Bl);

    float acc[4][4][4];
#pragma unroll
    for (int i = 0; i < 4; i++)
#pragma unroll
        for (int j = 0; j < 4; j++)
#pragma unroll
            for (int k = 0; k < 4; k++) acc[i][j][k] = 0.f;

    const int a_row_off = lane & 15;
    const int a_k_off   = (lane >> 4) * 8;
    const int b_row_off = (lane & 7) + ((lane >> 4) << 3);
    const int b_k_off   = ((lane >> 3) & 1) * 8;

    for (int c = 0; c < KDIM/32; c++) {
        __syncthreads();
        // ---- A tile: 128 rows x 32 fp32 -> bf16 hi/lo ----
#pragma unroll
        for (int j = 0; j < 4; j++) {
            int i = tid + 256*j;
            int row = i >> 3, c4 = i & 7;
            int gr = rowBase + row;
            float4 v = make_float4(0.f, 0.f, 0.f, 0.f);
            if (gr < M) v = *(const float4*)(A + (size_t)gr*KDIM + c*32 + c4*4);
            __nv_bfloat16 h0 = __float2bfloat16(v.x);
            __nv_bfloat16 h1 = __float2bfloat16(v.y);
            __nv_bfloat16 h2 = __float2bfloat16(v.z);
            __nv_bfloat16 h3 = __float2bfloat16(v.w);
            uint2 hh, ll;
            hh.x = pack_bf16(__bfloat162float(h0), __bfloat162float(h1));
            hh.y = pack_bf16(__bfloat162float(h2), __bfloat162float(h3));
            ll.x = pack_bf16(v.x - __bfloat162float(h0), v.y - __bfloat162float(h1));
            ll.y = pack_bf16(v.z - __bfloat162float(h2), v.w - __bfloat162float(h3));
            *(uint2*)&Ah[row*LDA + c4*4] = hh;
            *(uint2*)&Al[row*LDA + c4*4] = ll;
        }
        // ---- B tile: raw copy of pre-split bf16 (128 rows x 32 halves) ----
#pragma unroll
        for (int j = 0; j < 2; j++) {
            int i = tid + 256*j;
            int row = i >> 2, c8 = i & 3;
            const size_t gsrc = (size_t)(colBase + row)*KDIM + c*32 + c8*8;
            *(uint4*)&Bh[row*LDA + c8*8] = *(const uint4*)(Bth + gsrc);
            *(uint4*)&Bl[row*LDA + c8*8] = *(const uint4*)(Btl + gsrc);
        }
        __syncthreads();

#pragma unroll
        for (int ks = 0; ks < 2; ks++) {
            const int kb = ks * 16;
            uint32_t ah[4][4], al[4][4], bh[2][4], bl[2][4];
#pragma unroll
            for (int mt = 0; mt < 4; mt++) {
                int row = warpM*64 + mt*16 + a_row_off;
                uint32_t off = (uint32_t)(row*LDA + kb + a_k_off) * 2;
                ldm_x4(ah[mt], sAh + off);
                ldm_x4(al[mt], sAl + off);
            }
#pragma unroll
            for (int np = 0; np < 2; np++) {
                int row = warpN*32 + np*16 + b_row_off;
                uint32_t off = (uint32_t)(row*LDA + kb + b_k_off) * 2;
                ldm_x4(bh[np], sBh + off);
                ldm_x4(bl[np], sBl + off);
            }
#pragma unroll
            for (int mt = 0; mt < 4; mt++)
#pragma unroll
                for (int nt = 0; nt < 4; nt++) {
                    const uint32_t* Bhp = &bh[nt>>1][(nt&1)*2];
                    const uint32_t* Blp = &bl[nt>>1][(nt&1)*2];
                    mma_bf16(acc[mt][nt], ah[mt], Bhp);
                    mma_bf16(acc[mt][nt], al[mt], Bhp);
                    mma_bf16(acc[mt][nt], ah[mt], Blp);
                }
        }
    }

    // ---- epilogue ----
    const int g   = lane >> 2;
    const int tig = lane & 3;
#pragma unroll
    for (int mt = 0; mt < 4; mt++) {
        int r0 = rowBase + warpM*64 + mt*16 + g;
        int r1 = r0 + 8;
#pragma unroll
        for (int nt = 0; nt < 4; nt++) {
            int col = colBase + warpN*32 + nt*8 + tig*2;
            float2 v0 = make_float2(acc[mt][nt][0], acc[mt][nt][1]);
            float2 v1 = make_float2(acc[mt][nt][2], acc[mt][nt][3]);
            if (bias) {
                float b0 = bias[col], b1 = bias[col+1];
                v0.x += b0; v0.y += b1;
                v1.x += b0; v1.y += b1;
            }
            if (r0 < M) {
                if (Cadd) {
                    float2 rr = *(const float2*)(Cadd + (size_t)r0*Nglob + col);
                    v0.x += rr.x; v0.y += rr.y;
                }
                if constexpr (sizeof(OT) == 2)
                    *(__half2*)((__half*)C + (size_t)r0*Nglob + col) = __floats2half2_rn(v0.x, v0.y);
                else
                    *(float2*)((float*)C + (size_t)r0*Nglob + col) = v0;
            }
            if (r1 < M) {
                if (Cadd) {
                    float2 rr = *(const float2*)(Cadd + (size_t)r1*Nglob + col);
                    v1.x += rr.x; v1.y += rr.y;
                }
                if constexpr (sizeof(OT) == 2)
                    *(__half2*)((__half*)C + (size_t)r1*Nglob + col) = __floats2half2_rn(v1.x, v1.y);
                else
                    *(float2*)((float*)C + (size_t)r1*Nglob + col) = v1;
            }
        }
    }
}

// ---------------- LayerNorm: one warp per query row ----------------
__global__ void ln_kernel(const float* __restrict__ q,
                          const float* __restrict__ gamma,
                          const float* __restrict__ beta,
                          float* __restrict__ out)
{
    int warp = (blockIdx.x * blockDim.x + threadIdx.x) >> 5;
    int lane = threadIdx.x & 31;
    if (warp >= NQ) return;
    const float* row = q + (size_t)warp * EMBED;
    float v[8];
    float sum = 0.f;
#pragma unroll
    for (int i = 0; i < 8; i++) { v[i] = row[lane + i*32]; sum += v[i]; }
#pragma unroll
    for (int o = 16; o; o >>= 1) sum += __shfl_xor_sync(0xffffffffu, sum, o);
    float mean = sum * (1.0f/EMBED);
    float var = 0.f;
#pragma unroll
    for (int i = 0; i < 8; i++) { float d = v[i]-mean; var += d*d; }
#pragma unroll
    for (int o = 16; o; o >>= 1) var += __shfl_xor_sync(0xffffffffu, var, o);
    var *= (1.0f/EMBED);
    float inv = rsqrtf(var + 1e-5f);
    float* orow = out + (size_t)warp * EMBED;
#pragma unroll
    for (int i = 0; i < 8; i++) {
        int c = lane + i*32;
        orow[c] = (v[i]-mean)*inv*gamma[c] + beta[c];
    }
}

// ---------------- sampling: one block per query, one warp per head ----------------
__global__ __launch_bounds__(256)
void sample_kernel(const float* __restrict__ pos,
                   const int*   __restrict__ boff,
                   const int*   __restrict__ lshapes)
{
    int q    = blockIdx.x;
    int h    = threadIdx.x >> 5;
    int lane = threadIdx.x & 31;

    int b = (q >= boff[1]) ? 1 : 0;

    float posy = pos[q*2+0];
    float posx = pos[q*2+1];

    int   Hi[LEVELS], Wi[LEVELS];
    float Hf[LEVELS], Wf[LEVELS];
#pragma unroll
    for (int l = 0; l < LEVELS; l++) {
        Hi[l] = lshapes[l*2+0]; Wi[l] = lshapes[l*2+1];
        Hf[l] = (float)Hi[l];   Wf[l] = (float)Wi[l];
    }

    const float* alog = g_ofat + (size_t)q*384 + 256 + h*(LEVELS*POINTS);
    float logit = (lane < 16) ? alog[lane] : -1e30f;
    float mx = logit;
#pragma unroll
    for (int o = 8; o; o >>= 1) mx = fmaxf(mx, __shfl_xor_sync(0xffffffffu, mx, o));
    float e = (lane < 16) ? expf(logit - mx) : 0.f;
    float s = e;
#pragma unroll
    for (int o = 8; o; o >>= 1) s += __shfl_xor_sync(0xffffffffu, s, o);
    float aw = e / s;

    const float* offrow = g_ofat + (size_t)q*384 + h*(LEVELS*POINTS*2);

    float acc = 0.f;
#pragma unroll
    for (int lp = 0; lp < LEVELS*POINTS; lp++) {
        int l = lp >> 2;
        float a  = __shfl_sync(0xffffffffu, aw, lp);
        float oy = offrow[lp*2+0];
        float ox = offrow[lp*2+1];
        float hf = Hf[l], wf = Wf[l];
        float py = (posy + oy/hf)*hf - 0.5f;
        float px = (posx + ox/wf)*wf - 0.5f;
        float y0f = floorf(py), x0f = floorf(px);
        float wy = py - y0f,    wx = px - x0f;
        int y0 = (int)y0f, x0 = (int)x0f;
        int Hl = Hi[l],    Wl = Wi[l];

#pragma unroll
        for (int cc = 0; cc < 4; cc++) {
            int yi = y0 + (cc >> 1);
            int xi = x0 + (cc & 1);
            float w = ((cc >> 1) ? wy : (1.f-wy)) * ((cc & 1) ? wx : (1.f-wx));
            if (yi >= 0 && yi < Hl && xi >= 0 && xi < Wl) {
                size_t idx = ((((((size_t)b*HP + yi)*WP + xi)*LEVELS + l)*HEADS + h)
                              * HEAD_DIM) + lane;
                acc += a * w * __half2float(g_val[idx]);
            }
        }
    }
    g_samp[(size_t)q*EMBED + h*HEAD_DIM + lane] = acc;
}

// ---------------- launcher ----------------
extern "C" void kernel_launch(void* const* d_in, const int* in_sizes, int n_in,
                              void* d_out, int out_size)
{
    const float* query   = (const float*)d_in[0];
    const float* qpos    = (const float*)d_in[1];
    const int*   qboff   = (const int*)  d_in[2];
    const float* fmaps   = (const float*)d_in[3];
    const int*   lshapes = (const int*)  d_in[4];
    const float* gamma   = (const float*)d_in[5];
    const float* beta    = (const float*)d_in[6];
    const float* W_q     = (const float*)d_in[7];
    const float* W_off   = (const float*)d_in[8];
    const float* b_off   = (const float*)d_in[9];
    const float* W_attn  = (const float*)d_in[10];
    const float* b_attn  = (const float*)d_in[11];
    const float* W_val   = (const float*)d_in[12];
    const float* b_val   = (const float*)d_in[13];
    const float* W_out   = (const float*)d_in[14];
    float* out = (float*)d_out;

    float *xn, *xq, *ofat, *samp, *bofat;
    __half* val;
    __nv_bfloat16 *wth, *wtl;
    cudaGetSymbolAddress((void**)&xn,    g_xn);
    cudaGetSymbolAddress((void**)&xq,    g_xq);
    cudaGetSymbolAddress((void**)&ofat,  g_ofat);
    cudaGetSymbolAddress((void**)&val,   g_val);
    cudaGetSymbolAddress((void**)&samp,  g_samp);
    cudaGetSymbolAddress((void**)&wth,   g_wth);
    cudaGetSymbolAddress((void**)&wtl,   g_wtl);
    cudaGetSymbolAddress((void**)&bofat, g_bofat);

    __nv_bfloat16 *wq_h   = wth,          *wq_l   = wtl;
    __nv_bfloat16 *wof_h  = wth + 65536,  *wof_l  = wtl + 65536;   // rows 0-383
    __nv_bfloat16 *wval_h = wth + 163840, *wval_l = wtl + 163840;
    __nv_bfloat16 *wout_h = wth + 229376, *wout_l = wtl + 229376;

    // 0) transpose + split weights; concat biases
    {
        dim3 blk(32, 8);
        transpose_split<<<dim3(8, 8), blk>>>(W_q,    wq_h,   wq_l,   256);
        transpose_split<<<dim3(8, 8), blk>>>(W_off,  wof_h,  wof_l,  256);
        transpose_split<<<dim3(4, 8), blk>>>(W_attn, wof_h + 256*256, wof_l + 256*256, 128);
        transpose_split<<<dim3(8, 8), blk>>>(W_val,  wval_h, wval_l, 256);
        transpose_split<<<dim3(8, 8), blk>>>(W_out,  wout_h, wout_l, 256);
        bias_concat<<<2, 192>>>(b_off, b_attn);
    }

    // 1) LayerNorm
    ln_kernel<<<(NQ*32 + 255)/256, 256>>>(query, gamma, beta, xn);

    const int MQT = (NQ + 127) / 128;  // 157

    // 2) xq = xn @ W_q
    mma_gemm<float><<<dim3(2, MQT), 256>>>(xn, wq_h, wq_l, nullptr, nullptr, xq, NQ, 256);

    // 3) [off|attn] = xq @ [W_off|W_attn] + [b_off|b_attn]  (fused, N=384)
    mma_gemm<float><<<dim3(3, MQT), 256>>>(xq, wof_h, wof_l, bofat, nullptr, ofat, NQ, 384);

    // 4) value = fmaps @ W_val + b_val  -> fp16 (dominant GEMM)
    mma_gemm<__half><<<dim3(2, NVAL/128), 256>>>(fmaps, wval_h, wval_l, b_val, nullptr, val, NVAL, 256);

    // 5) softmax + bilinear sampling
    sample_kernel<<<NQ, 256>>>(qpos, qboff, lshapes);

    // 6) out = samp @ W_out + residual
    mma_gemm<float><<<dim3(2, MQT), 256>>>(samp, wout_h, wout_l, nullptr, query, out, NQ, 256);
}

// round 5
// speedup vs baseline: 1.7515x; 1.1098x over previous
#include <cuda_runtime.h>
#include <cuda_bf16.h>
#include <cuda_fp16.h>
#include <math.h>
#include <stdint.h>

#define EMBED    256
#define HEADS    8
#define LEVELS   4
#define POINTS   4
#define HEAD_DIM 32
#define NQ       20000
#define NB       2
#define HP       128
#define WP       128
#define NVAL     (NB*HP*WP*LEVELS)   // 131072
#define KDIM     256

// ---------------- device scratch (static, no allocations) ----------------
__device__ __nv_bfloat16 g_xnh [NQ*EMBED];
__device__ __nv_bfloat16 g_xnl [NQ*EMBED];
__device__ __nv_bfloat16 g_xqh [NQ*EMBED];
__device__ __nv_bfloat16 g_xql [NQ*EMBED];
__device__ float         g_ofat[NQ*384];               // [off(256) | attn(128)]
__device__ __nv_bfloat16 g_fmh [(size_t)NVAL*EMBED];   // fmaps split hi
__device__ __nv_bfloat16 g_fml [(size_t)NVAL*EMBED];   // fmaps split lo
__device__ __half        g_val [(size_t)NVAL*EMBED];   // projected value fp16
__device__ __nv_bfloat16 g_smh [NQ*EMBED];
__device__ __nv_bfloat16 g_sml [NQ*EMBED];
__device__ __nv_bfloat16 g_wth [294912];               // wq|wofat|wval|wout
__device__ __nv_bfloat16 g_wtl [294912];
__device__ float         g_bofat[384];

// ---------------- helpers ----------------
__device__ __forceinline__ uint32_t smem_u32(const void* p) {
    uint32_t a;
    asm("{ .reg .u64 t; cvta.to.shared.u64 t, %1; cvt.u32.u64 %0, t; }" : "=r"(a) : "l"(p));
    return a;
}
__device__ __forceinline__ void ldm_x4(uint32_t* r, uint32_t addr) {
    asm volatile("ldmatrix.sync.aligned.m8n8.x4.shared.b16 {%0,%1,%2,%3}, [%4];"
                 : "=r"(r[0]), "=r"(r[1]), "=r"(r[2]), "=r"(r[3]) : "r"(addr));
}
__device__ __forceinline__ void mma_bf16(float* c, const uint32_t* a, const uint32_t* b) {
    asm volatile("mma.sync.aligned.m16n8k16.row.col.f32.bf16.bf16.f32 "
                 "{%0,%1,%2,%3},{%4,%5,%6,%7},{%8,%9},{%0,%1,%2,%3};"
                 : "+f"(c[0]), "+f"(c[1]), "+f"(c[2]), "+f"(c[3])
                 : "r"(a[0]), "r"(a[1]), "r"(a[2]), "r"(a[3]), "r"(b[0]), "r"(b[1]));
}
__device__ __forceinline__ void cp16(uint32_t dst, const __nv_bfloat16* src, bool pred) {
    size_t g = __cvta_generic_to_global(src);
    int sz = pred ? 16 : 0;
    asm volatile("cp.async.cg.shared.global [%0], [%1], 16, %2;"
                 :: "r"(dst), "l"(g), "r"(sz) : "memory");
}
#define CP_COMMIT() asm volatile("cp.async.commit_group;" ::: "memory")
#define CP_WAIT0()  asm volatile("cp.async.wait_group 0;" ::: "memory")

// ---------------- transpose + bf16 hi/lo split: src[256,N] -> dst[N,256] ----------------
__global__ void transpose_split(const float* __restrict__ src,
                                __nv_bfloat16* __restrict__ dh,
                                __nv_bfloat16* __restrict__ dl, int N)
{
    __shared__ float t[32][33];
    int bx = blockIdx.x * 32;
    int by = blockIdx.y * 32;
#pragma unroll
    for (int i = 0; i < 4; i++) {
        int y = by + threadIdx.y + i*8;
        t[threadIdx.y + i*8][threadIdx.x] = src[(size_t)y*N + bx + threadIdx.x];
    }
    __syncthreads();
#pragma unroll
    for (int i = 0; i < 4; i++) {
        int row = bx + threadIdx.y + i*8;
        float v = t[threadIdx.x][threadIdx.y + i*8];
        __nv_bfloat16 h = __float2bfloat16(v);
        dh[(size_t)row*256 + by + threadIdx.x] = h;
        dl[(size_t)row*256 + by + threadIdx.x] = __float2bfloat16(v - __bfloat162float(h));
    }
}

// ---------------- streaming fp32 -> bf16 hi/lo split ----------------
__global__ void split_kernel(const float* __restrict__ src,
                             __nv_bfloat16* __restrict__ dh,
                             __nv_bfloat16* __restrict__ dl, size_t n4)
{
    size_t i = blockIdx.x * (size_t)blockDim.x + threadIdx.x;
    if (i >= n4) return;
    float4 v = *(const float4*)(src + i*4);
    __nv_bfloat16 h0 = __float2bfloat16(v.x);
    __nv_bfloat16 h1 = __float2bfloat16(v.y);
    __nv_bfloat16 h2 = __float2bfloat16(v.z);
    __nv_bfloat16 h3 = __float2bfloat16(v.w);
    __nv_bfloat162 hh0 = {h0, h1}, hh1 = {h2, h3};
    __nv_bfloat162 ll0 = {__float2bfloat16(v.x - __bfloat162float(h0)),
                          __float2bfloat16(v.y - __bfloat162float(h1))};
    __nv_bfloat162 ll1 = {__float2bfloat16(v.z - __bfloat162float(h2)),
                          __float2bfloat16(v.w - __bfloat162float(h3))};
    *(uint2*)(dh + i*4) = make_uint2(*(uint32_t*)&hh0, *(uint32_t*)&hh1);
    *(uint2*)(dl + i*4) = make_uint2(*(uint32_t*)&ll0, *(uint32_t*)&ll1);
}

__global__ void bias_concat(const float* __restrict__ b_off, const float* __restrict__ b_attn)
{
    int i = threadIdx.x + blockIdx.x*blockDim.x;
    if (i < 384) g_bofat[i] = (i < 256) ? b_off[i] : b_attn[i-256];
}

// ---------------- pipelined bf16x3 mma.sync GEMM ----------------
// C[M,Nglob] = (Ath+Atl)[M,256] @ (Bth+Btl)[Nglob,256]^T (+bias) (+Cadd)
// OM: 0 = fp32 out, 1 = fp16 out, 2 = split bf16 out
#define LDA 40
#define ARR 10240                   // bytes per smem array
#define STG (4*ARR)                 // bytes per stage
template<int OM>
__global__ __launch_bounds__(256, 2)
void mma_gemm(const __nv_bfloat16* __restrict__ Ath, const __nv_bfloat16* __restrict__ Atl,
              const __nv_bfloat16* __restrict__ Bth, const __nv_bfloat16* __restrict__ Btl,
              const float* __restrict__ bias, const float* __restrict__ Cadd,
              float* __restrict__ Cf, __half* __restrict__ Ch16,
              __nv_bfloat16* __restrict__ Cbh, __nv_bfloat16* __restrict__ Cbl,
              int M, int Nglob)
{
    extern __shared__ __align__(16) char smem[];
    const uint32_t sb = smem_u32(smem);

    const int tid  = threadIdx.x;
    const int wid  = tid >> 5;
    const int lane = tid & 31;
    const int warpM = wid & 1;
    const int warpN = wid >> 1;
    const int rowBase = blockIdx.y * 128;
    const int colBase = blockIdx.x * 128;

    // copy indices (per-thread): 2 iters x 4 arrays, 16B each
    const int cp_row = tid >> 2;        // 0..63 (+64 on second iter)
    const int cp_c8  = (tid & 3) * 8;   // halves offset 0,8,16,24

    float acc[4][4][4];
#pragma unroll
    for (int i = 0; i < 4; i++)
#pragma unroll
        for (int j = 0; j < 4; j++)
#pragma unroll
            for (int k = 0; k < 4; k++) acc[i][j][k] = 0.f;

    const int a_row_off = lane & 15;
    const int a_k_off   = (lane >> 4) * 8;
    const int b_row_off = (lane & 7) + ((lane >> 4) << 3);
    const int b_k_off   = ((lane >> 3) & 1) * 8;

    auto copy_chunk = [&](int c, int stage) {
        const uint32_t s0 = sb + stage*STG;
#pragma unroll
        for (int j = 0; j < 2; j++) {
            int row = cp_row + j*64;
            uint32_t so = (uint32_t)(row*LDA + cp_c8) * 2;
            int ga = rowBase + row;
            size_t gao = (size_t)ga*KDIM + c*32 + cp_c8;
            bool pa = (ga < M);
            cp16(s0 +         so, Ath + gao, pa);
            cp16(s0 + ARR   + so, Atl + gao, pa);
            size_t gbo = (size_t)(colBase + row)*KDIM + c*32 + cp_c8;
            cp16(s0 + 2*ARR + so, Bth + gbo, true);
            cp16(s0 + 3*ARR + so, Btl + gbo, true);
        }
        CP_COMMIT();
    };

    copy_chunk(0, 0);
    CP_WAIT0();
    __syncthreads();

    for (int c = 0; c < KDIM/32; c++) {
        const int s = c & 1;
        if (c < KDIM/32 - 1) copy_chunk(c + 1, s ^ 1);

        const uint32_t aB = sb + s*STG;
        const uint32_t bB = aB + 2*ARR;
#pragma unroll
        for (int ks = 0; ks < 2; ks++) {
            const int kb = ks * 16;
            uint32_t bh[2][4], bl[2][4];
#pragma unroll
            for (int np = 0; np < 2; np++) {
                int row = warpN*32 + np*16 + b_row_off;
                uint32_t off = (uint32_t)(row*LDA + kb + b_k_off) * 2;
                ldm_x4(bh[np], bB + off);
                ldm_x4(bl[np], bB + ARR + off);
            }
#pragma unroll
            for (int mt = 0; mt < 4; mt++) {
                uint32_t ah[4], al[4];
                int row = warpM*64 + mt*16 + a_row_off;
                uint32_t off = (uint32_t)(row*LDA + kb + a_k_off) * 2;
                ldm_x4(ah, aB + off);
                ldm_x4(al, aB + ARR + off);
#pragma unroll
                for (int nt = 0; nt < 4; nt++) {
                    const uint32_t* Bhp = &bh[nt>>1][(nt&1)*2];
                    const uint32_t* Blp = &bl[nt>>1][(nt&1)*2];
                    mma_bf16(acc[mt][nt], ah, Bhp);
                    mma_bf16(acc[mt][nt], al, Bhp);
                    mma_bf16(acc[mt][nt], ah, Blp);
                }
            }
        }
        if (c < KDIM/32 - 1) {
            CP_WAIT0();
            __syncthreads();
        }
    }

    // ---- epilogue ----
    const int g   = lane >> 2;
    const int tig = lane & 3;
#pragma unroll
    for (int mt = 0; mt < 4; mt++) {
#pragma unroll
        for (int half = 0; half < 2; half++) {
            int r = rowBase + warpM*64 + mt*16 + g + half*8;
            if (r >= M) continue;
#pragma unroll
            for (int nt = 0; nt < 4; nt++) {
                int col = colBase + warpN*32 + nt*8 + tig*2;
                float vx = acc[mt][nt][half*2+0];
                float vy = acc[mt][nt][half*2+1];
                if (bias) { vx += bias[col]; vy += bias[col+1]; }
                if (Cadd) {
                    float2 rr = *(const float2*)(Cadd + (size_t)r*Nglob + col);
                    vx += rr.x; vy += rr.y;
                }
                if (OM == 0) {
                    *(float2*)(Cf + (size_t)r*Nglob + col) = make_float2(vx, vy);
                } else if (OM == 1) {
                    *(__half2*)(Ch16 + (size_t)r*Nglob + col) = __floats2half2_rn(vx, vy);
                } else {
                    __nv_bfloat16 hx = __float2bfloat16(vx);
                    __nv_bfloat16 hy = __float2bfloat16(vy);
                    __nv_bfloat162 hh = {hx, hy};
                    __nv_bfloat162 ll = {__float2bfloat16(vx - __bfloat162float(hx)),
                                         __float2bfloat16(vy - __bfloat162float(hy))};
                    *(__nv_bfloat162*)(Cbh + (size_t)r*Nglob + col) = hh;
                    *(__nv_bfloat162*)(Cbl + (size_t)r*Nglob + col) = ll;
                }
            }
        }
    }
}

// ---------------- LayerNorm -> split bf16 ----------------
__global__ void ln_kernel(const float* __restrict__ q,
                          const float* __restrict__ gamma,
                          const float* __restrict__ beta)
{
    int warp = (blockIdx.x * blockDim.x + threadIdx.x) >> 5;
    int lane = threadIdx.x & 31;
    if (warp >= NQ) return;
    const float* row = q + (size_t)warp * EMBED;
    float v[8];
    float sum = 0.f;
#pragma unroll
    for (int i = 0; i < 8; i++) { v[i] = row[lane + i*32]; sum += v[i]; }
#pragma unroll
    for (int o = 16; o; o >>= 1) sum += __shfl_xor_sync(0xffffffffu, sum, o);
    float mean = sum * (1.0f/EMBED);
    float var = 0.f;
#pragma unroll
    for (int i = 0; i < 8; i++) { float d = v[i]-mean; var += d*d; }
#pragma unroll
    for (int o = 16; o; o >>= 1) var += __shfl_xor_sync(0xffffffffu, var, o);
    var *= (1.0f/EMBED);
    float inv = rsqrtf(var + 1e-5f);
#pragma unroll
    for (int i = 0; i < 8; i++) {
        int c = lane + i*32;
        float y = (v[i]-mean)*inv*gamma[c] + beta[c];
        __nv_bfloat16 h = __float2bfloat16(y);
        g_xnh[(size_t)warp*EMBED + c] = h;
        g_xnl[(size_t)warp*EMBED + c] = __float2bfloat16(y - __bfloat162float(h));
    }
}

// ---------------- sampling -> split bf16 ----------------
__global__ __launch_bounds__(256)
void sample_kernel(const float* __restrict__ pos,
                   const int*   __restrict__ boff,
                   const int*   __restrict__ lshapes)
{
    int q    = blockIdx.x;
    int h    = threadIdx.x >> 5;
    int lane = threadIdx.x & 31;

    int b = (q >= boff[1]) ? 1 : 0;

    float posy = pos[q*2+0];
    float posx = pos[q*2+1];

    int   Hi[LEVELS], Wi[LEVELS];
    float Hf[LEVELS], Wf[LEVELS];
#pragma unroll
    for (int l = 0; l < LEVELS; l++) {
        Hi[l] = lshapes[l*2+0]; Wi[l] = lshapes[l*2+1];
        Hf[l] = (float)Hi[l];   Wf[l] = (float)Wi[l];
    }

    const float* alog = g_ofat + (size_t)q*384 + 256 + h*(LEVELS*POINTS);
    float logit = (lane < 16) ? alog[lane] : -1e30f;
    float mx = logit;
#pragma unroll
    for (int o = 8; o; o >>= 1) mx = fmaxf(mx, __shfl_xor_sync(0xffffffffu, mx, o));
    float e = (lane < 16) ? expf(logit - mx) : 0.f;
    float s = e;
#pragma unroll
    for (int o = 8; o; o >>= 1) s += __shfl_xor_sync(0xffffffffu, s, o);
    float aw = e / s;

    const float* offrow = g_ofat + (size_t)q*384 + h*(LEVELS*POINTS*2);

    float acc = 0.f;
#pragma unroll
    for (int lp = 0; lp < LEVELS*POINTS; lp++) {
        int l = lp >> 2;
        float a  = __shfl_sync(0xffffffffu, aw, lp);
        float oy = offrow[lp*2+0];
        float ox = offrow[lp*2+1];
        float hf = Hf[l], wf = Wf[l];
        float py = (posy + oy/hf)*hf - 0.5f;
        float px = (posx + ox/wf)*wf - 0.5f;
        float y0f = floorf(py), x0f = floorf(px);
        float wy = py - y0f,    wx = px - x0f;
        int y0 = (int)y0f, x0 = (int)x0f;
        int Hl = Hi[l],    Wl = Wi[l];

#pragma unroll
        for (int cc = 0; cc < 4; cc++) {
            int yi = y0 + (cc >> 1);
            int xi = x0 + (cc & 1);
            float w = ((cc >> 1) ? wy : (1.f-wy)) * ((cc & 1) ? wx : (1.f-wx));
            if (yi >= 0 && yi < Hl && xi >= 0 && xi < Wl) {
                size_t idx = ((((((size_t)b*HP + yi)*WP + xi)*LEVELS + l)*HEADS + h)
                              * HEAD_DIM) + lane;
                acc += a * w * __half2float(g_val[idx]);
            }
        }
    }
    __nv_bfloat16 hv = __float2bfloat16(acc);
    g_smh[(size_t)q*EMBED + h*HEAD_DIM + lane] = hv;
    g_sml[(size_t)q*EMBED + h*HEAD_DIM + lane] = __float2bfloat16(acc - __bfloat162float(hv));
}

// ---------------- launcher ----------------
extern "C" void kernel_launch(void* const* d_in, const int* in_sizes, int n_in,
                              void* d_out, int out_size)
{
    const float* query   = (const float*)d_in[0];
    const float* qpos    = (const float*)d_in[1];
    const int*   qboff   = (const int*)  d_in[2];
    const float* fmaps   = (const float*)d_in[3];
    const int*   lshapes = (const int*)  d_in[4];
    const float* gamma   = (const float*)d_in[5];
    const float* beta    = (const float*)d_in[6];
    const float* W_q     = (const float*)d_in[7];
    const float* W_off   = (const float*)d_in[8];
    const float* b_off   = (const float*)d_in[9];
    const float* W_attn  = (const float*)d_in[10];
    const float* b_attn  = (const float*)d_in[11];
    const float* W_val   = (const float*)d_in[12];
    const float* b_val   = (const float*)d_in[13];
    const float* W_out   = (const float*)d_in[14];
    float* out = (float*)d_out;

    __nv_bfloat16 *xnh, *xnl, *xqh, *xql, *fmh, *fml, *smh, *sml, *wth, *wtl;
    float *ofat, *bofat;
    __half* val;
    cudaGetSymbolAddress((void**)&xnh,  g_xnh);
    cudaGetSymbolAddress((void**)&xnl,  g_xnl);
    cudaGetSymbolAddress((void**)&xqh,  g_xqh);
    cudaGetSymbolAddress((void**)&xql,  g_xql);
    cudaGetSymbolAddress((void**)&ofat, g_ofat);
    cudaGetSymbolAddress((void**)&fmh,  g_fmh);
    cudaGetSymbolAddress((void**)&fml,  g_fml);
    cudaGetSymbolAddress((void**)&val,  g_val);
    cudaGetSymbolAddress((void**)&smh,  g_smh);
    cudaGetSymbolAddress((void**)&sml,  g_sml);
    cudaGetSymbolAddress((void**)&wth,  g_wth);
    cudaGetSymbolAddress((void**)&wtl,  g_wtl);
    cudaGetSymbolAddress((void**)&bofat, g_bofat);

    __nv_bfloat16 *wq_h   = wth,          *wq_l   = wtl;
    __nv_bfloat16 *wof_h  = wth + 65536,  *wof_l  = wtl + 65536;
    __nv_bfloat16 *wval_h = wth + 163840, *wval_l = wtl + 163840;
    __nv_bfloat16 *wout_h = wth + 229376, *wout_l = wtl + 229376;

    const int SMEM = 2*STG;  // 81920
    cudaFuncSetAttribute(mma_gemm<0>, cudaFuncAttributeMaxDynamicSharedMemorySize, SMEM);
    cudaFuncSetAttribute(mma_gemm<1>, cudaFuncAttributeMaxDynamicSharedMemorySize, SMEM);
    cudaFuncSetAttribute(mma_gemm<2>, cudaFuncAttributeMaxDynamicSharedMemorySize, SMEM);

    dim3 tblk(32, 8);
    const int MQT = (NQ + 127) / 128;  // 157

    // 1) W_val transpose+split
    transpose_split<<<dim3(8, 8), tblk>>>(W_val, wval_h, wval_l, 256);
    // 2) fmaps split (streaming)
    split_kernel<<<((size_t)NVAL*EMBED/4 + 255)/256, 256>>>(fmaps, fmh, fml, (size_t)NVAL*EMBED/4);
    // 3) LayerNorm -> split xn
    ln_kernel<<<(NQ*32 + 255)/256, 256>>>(query, gamma, beta);
    // 4) bias concat
    bias_concat<<<2, 192>>>(b_off, b_attn);
    // 5) W_q transpose+split
    transpose_split<<<dim3(8, 8), tblk>>>(W_q, wq_h, wq_l, 256);
    // 6) value GEMM (captured by ncu -s 5 -c 1)
    mma_gemm<1><<<dim3(2, NVAL/128), 256, SMEM>>>(fmh, fml, wval_h, wval_l, b_val, nullptr,
                                                  nullptr, val, nullptr, nullptr, NVAL, 256);
    // 7-9) remaining weight transposes
    transpose_split<<<dim3(8, 8), tblk>>>(W_off,  wof_h,           wof_l,           256);
    transpose_split<<<dim3(4, 8), tblk>>>(W_attn, wof_h + 256*256, wof_l + 256*256, 128);
    transpose_split<<<dim3(8, 8), tblk>>>(W_out,  wout_h,          wout_l,          256);
    // 10) xq = xn @ W_q  -> split bf16
    mma_gemm<2><<<dim3(2, MQT), 256, SMEM>>>(xnh, xnl, wq_h, wq_l, nullptr, nullptr,
                                             nullptr, nullptr, xqh, xql, NQ, 256);
    // 11) [off|attn] = xq @ [W_off|W_attn] + bias  -> fp32
    mma_gemm<0><<<dim3(3, MQT), 256, SMEM>>>(xqh, xql, wof_h, wof_l, bofat, nullptr,
                                             ofat, nullptr, nullptr, nullptr, NQ, 384);
    // 12) softmax + bilinear sampling -> split bf16
    sample_kernel<<<NQ, 256>>>(qpos, qboff, lshapes);
    // 13) out = samp @ W_out + residual -> fp32
    mma_gemm<0><<<dim3(2, MQT), 256, SMEM>>>(smh, sml, wout_h, wout_l, nullptr, query,
                                             out, nullptr, nullptr, nullptr, NQ, 256);
}

// round 6
// speedup vs baseline: 2.8124x; 1.6058x over previous
#include <cuda_runtime.h>
#include <cuda_bf16.h>
#include <cuda_fp16.h>
#include <math.h>
#include <stdint.h>

#define EMBED    256
#define HEADS    8
#define LEVELS   4
#define POINTS   4
#define HEAD_DIM 32
#define NQ       20000
#define NB       2
#define HP       128
#define WP       128
#define NVAL     (NB*HP*WP*LEVELS)   // 131072
#define KDIM     256

// ---------------- device scratch (static, no allocations) ----------------
__device__ __nv_bfloat16 g_xnh [NQ*EMBED];
__device__ __nv_bfloat16 g_xnl [NQ*EMBED];
__device__ __nv_bfloat16 g_xqh [NQ*EMBED];
__device__ __nv_bfloat16 g_xql [NQ*EMBED];
__device__ float         g_ofat[NQ*384];               // [off(256) | attn(128)]
__device__ __half        g_val [(size_t)NVAL*EMBED];   // projected value fp16
__device__ __nv_bfloat16 g_smh [NQ*EMBED];
__device__ __nv_bfloat16 g_sml [NQ*EMBED];
__device__ __nv_bfloat16 g_wth [229376];               // wq | wofat | wout (bf16 hi)
__device__ __nv_bfloat16 g_wtl [229376];               // lo
__device__ __half        g_wv16[65536];                // W_val fp16 K-major
__device__ float         g_bofat[384];

// ---------------- helpers ----------------
__device__ __forceinline__ uint32_t smem_u32(const void* p) {
    uint32_t a;
    asm("{ .reg .u64 t; cvta.to.shared.u64 t, %1; cvt.u32.u64 %0, t; }" : "=r"(a) : "l"(p));
    return a;
}
__device__ __forceinline__ void ldm_x4(uint32_t* r, uint32_t addr) {
    asm volatile("ldmatrix.sync.aligned.m8n8.x4.shared.b16 {%0,%1,%2,%3}, [%4];"
                 : "=r"(r[0]), "=r"(r[1]), "=r"(r[2]), "=r"(r[3]) : "r"(addr));
}
__device__ __forceinline__ void mma_bf16(float* c, const uint32_t* a, const uint32_t* b) {
    asm volatile("mma.sync.aligned.m16n8k16.row.col.f32.bf16.bf16.f32 "
                 "{%0,%1,%2,%3},{%4,%5,%6,%7},{%8,%9},{%0,%1,%2,%3};"
                 : "+f"(c[0]), "+f"(c[1]), "+f"(c[2]), "+f"(c[3])
                 : "r"(a[0]), "r"(a[1]), "r"(a[2]), "r"(a[3]), "r"(b[0]), "r"(b[1]));
}
__device__ __forceinline__ void mma_f16(float* c, const uint32_t* a, const uint32_t* b) {
    asm volatile("mma.sync.aligned.m16n8k16.row.col.f32.f16.f16.f32 "
                 "{%0,%1,%2,%3},{%4,%5,%6,%7},{%8,%9},{%0,%1,%2,%3};"
                 : "+f"(c[0]), "+f"(c[1]), "+f"(c[2]), "+f"(c[3])
                 : "r"(a[0]), "r"(a[1]), "r"(a[2]), "r"(a[3]), "r"(b[0]), "r"(b[1]));
}
__device__ __forceinline__ void cp16(uint32_t dst, const void* src, bool pred) {
    size_t g = __cvta_generic_to_global(src);
    int sz = pred ? 16 : 0;
    asm volatile("cp.async.cg.shared.global [%0], [%1], 16, %2;"
                 :: "r"(dst), "l"(g), "r"(sz) : "memory");
}
#define CP_COMMIT() asm volatile("cp.async.commit_group;" ::: "memory")
#define CP_WAIT0()  asm volatile("cp.async.wait_group 0;" ::: "memory")

// ---------------- transpose + bf16 hi/lo split: src[256,N] -> dst[N,256] ----------------
__global__ void transpose_split(const float* __restrict__ src,
                                __nv_bfloat16* __restrict__ dh,
                                __nv_bfloat16* __restrict__ dl, int N)
{
    __shared__ float t[32][33];
    int bx = blockIdx.x * 32;
    int by = blockIdx.y * 32;
#pragma unroll
    for (int i = 0; i < 4; i++) {
        int y = by + threadIdx.y + i*8;
        t[threadIdx.y + i*8][threadIdx.x] = src[(size_t)y*N + bx + threadIdx.x];
    }
    __syncthreads();
#pragma unroll
    for (int i = 0; i < 4; i++) {
        int row = bx + threadIdx.y + i*8;
        float v = t[threadIdx.x][threadIdx.y + i*8];
        __nv_bfloat16 h = __float2bfloat16(v);
        dh[(size_t)row*256 + by + threadIdx.x] = h;
        dl[(size_t)row*256 + by + threadIdx.x] = __float2bfloat16(v - __bfloat162float(h));
    }
}

// ---------------- transpose to fp16: src[256,256] -> dst[256,256] ----------------
__global__ void transpose_f16(const float* __restrict__ src, __half* __restrict__ dst)
{
    __shared__ float t[32][33];
    int bx = blockIdx.x * 32;
    int by = blockIdx.y * 32;
#pragma unroll
    for (int i = 0; i < 4; i++) {
        int y = by + threadIdx.y + i*8;
        t[threadIdx.y + i*8][threadIdx.x] = src[(size_t)y*256 + bx + threadIdx.x];
    }
    __syncthreads();
#pragma unroll
    for (int i = 0; i < 4; i++) {
        int row = bx + threadIdx.y + i*8;
        dst[(size_t)row*256 + by + threadIdx.x] = __float2half(t[threadIdx.x][threadIdx.y + i*8]);
    }
}

__global__ void bias_concat(const float* __restrict__ b_off, const float* __restrict__ b_attn)
{
    int i = threadIdx.x + blockIdx.x*blockDim.x;
    if (i < 384) g_bofat[i] = (i < 256) ? b_off[i] : b_attn[i-256];
}

#define LDA 40
// ---------------- fp16 value GEMM with fused fp32->fp16 convert ----------------
// C[NVAL,256] = fp16(A_fp32[NVAL,256]) @ Bt_fp16[256,256]^T + bias
// smem: A32 staging 2x16384 | B 2x10240 | F16A 10240   (= 63488 B)
__global__ __launch_bounds__(256, 2)
void val_gemm(const float* __restrict__ A, const __half* __restrict__ Bt,
              const float* __restrict__ bias, __half* __restrict__ C)
{
    extern __shared__ __align__(16) char sm[];
    const uint32_t sb   = smem_u32(sm);
    const uint32_t A32  = sb;
    const uint32_t Bst  = sb + 32768;
    const uint32_t F16A = sb + 32768 + 20480;
    char* smF16 = sm + 32768 + 20480;

    const int tid  = threadIdx.x;
    const int wid  = tid >> 5;
    const int lane = tid & 31;
    const int warpM = wid & 1;
    const int warpN = wid >> 1;
    const int rowBase = blockIdx.y * 128;
    const int colBase = blockIdx.x * 128;

    float acc[4][4][4];
#pragma unroll
    for (int i = 0; i < 4; i++)
#pragma unroll
        for (int j = 0; j < 4; j++)
#pragma unroll
            for (int k = 0; k < 4; k++) acc[i][j][k] = 0.f;

    const int a_row_off = lane & 15;
    const int a_k_off   = (lane >> 4) * 8;
    const int b_row_off = (lane & 7) + ((lane >> 4) << 3);
    const int b_k_off   = ((lane >> 3) & 1) * 8;

    auto copy_chunk = [&](int c, int st) {
#pragma unroll
        for (int j = 0; j < 4; j++) {               // A fp32: 1024 x 16B
            int id = j*256 + tid;
            int row = id >> 3, c4 = (id & 7) << 2;
            cp16(A32 + st*16384 + id*16,
                 A + (size_t)(rowBase + row)*KDIM + c*32 + c4, true);
        }
#pragma unroll
        for (int j = 0; j < 2; j++) {               // B fp16: 512 x 16B
            int id = j*256 + tid;
            int row = id >> 2, c8 = (id & 3) * 8;
            cp16(Bst + st*10240 + (uint32_t)(row*LDA + c8)*2,
                 Bt + (size_t)(colBase + row)*KDIM + c*32 + c8, true);
        }
        CP_COMMIT();
    };
    auto convert = [&](int st) {
#pragma unroll
        for (int j = 0; j < 4; j++) {
            int id = j*256 + tid;
            int row = id >> 3, c4 = (id & 7) << 2;
            float4 v = *(const float4*)(sm + st*16384 + id*16);
            __half2 p0 = __floats2half2_rn(v.x, v.y);
            __half2 p1 = __floats2half2_rn(v.z, v.w);
            *(uint2*)(smF16 + (uint32_t)(row*LDA + c4)*2) =
                make_uint2(*(uint32_t*)&p0, *(uint32_t*)&p1);
        }
    };

    copy_chunk(0, 0);
    CP_WAIT0();
    __syncthreads();
    convert(0);
    __syncthreads();

    for (int c = 0; c < KDIM/32; c++) {
        const int s = c & 1;
        if (c < KDIM/32 - 1) copy_chunk(c + 1, s ^ 1);

        const uint32_t bB = Bst + s*10240;
#pragma unroll
        for (int ks = 0; ks < 2; ks++) {
            const int kb = ks * 16;
            uint32_t bh[2][4];
#pragma unroll
            for (int np = 0; np < 2; np++) {
                int row = warpN*32 + np*16 + b_row_off;
                ldm_x4(bh[np], bB + (uint32_t)(row*LDA + kb + b_k_off)*2);
            }
#pragma unroll
            for (int mt = 0; mt < 4; mt++) {
                uint32_t ah[4];
                int row = warpM*64 + mt*16 + a_row_off;
                ldm_x4(ah, F16A + (uint32_t)(row*LDA + kb + a_k_off)*2);
#pragma unroll
                for (int nt = 0; nt < 4; nt++)
                    mma_f16(acc[mt][nt], ah, &bh[nt>>1][(nt&1)*2]);
            }
        }
        if (c < KDIM/32 - 1) {
            CP_WAIT0();
            __syncthreads();
            convert(s ^ 1);
            __syncthreads();
        }
    }

    const int g   = lane >> 2;
    const int tig = lane & 3;
#pragma unroll
    for (int mt = 0; mt < 4; mt++)
#pragma unroll
        for (int hf = 0; hf < 2; hf++) {
            int r = rowBase + warpM*64 + mt*16 + g + hf*8;
#pragma unroll
            for (int nt = 0; nt < 4; nt++) {
                int col = colBase + warpN*32 + nt*8 + tig*2;
                float vx = acc[mt][nt][hf*2+0] + bias[col];
                float vy = acc[mt][nt][hf*2+1] + bias[col+1];
                *(__half2*)(C + (size_t)r*256 + col) = __floats2half2_rn(vx, vy);
            }
        }
}

// ---------------- pipelined bf16x3 mma.sync GEMM (query-side) ----------------
#define ARR 10240
#define STG (4*ARR)
template<int OM>   // 0 = fp32 out, 2 = split bf16 out
__global__ __launch_bounds__(256, 2)
void mma_gemm(const __nv_bfloat16* __restrict__ Ath, const __nv_bfloat16* __restrict__ Atl,
              const __nv_bfloat16* __restrict__ Bth, const __nv_bfloat16* __restrict__ Btl,
              const float* __restrict__ bias, const float* __restrict__ Cadd,
              float* __restrict__ Cf,
              __nv_bfloat16* __restrict__ Cbh, __nv_bfloat16* __restrict__ Cbl,
              int M, int Nglob)
{
    extern __shared__ __align__(16) char smem[];
    const uint32_t sb = smem_u32(smem);

    const int tid  = threadIdx.x;
    const int wid  = tid >> 5;
    const int lane = tid & 31;
    const int warpM = wid & 1;
    const int warpN = wid >> 1;
    const int rowBase = blockIdx.y * 128;
    const int colBase = blockIdx.x * 128;

    const int cp_row = tid >> 2;
    const int cp_c8  = (tid & 3) * 8;

    float acc[4][4][4];
#pragma unroll
    for (int i = 0; i < 4; i++)
#pragma unroll
        for (int j = 0; j < 4; j++)
#pragma unroll
            for (int k = 0; k < 4; k++) acc[i][j][k] = 0.f;

    const int a_row_off = lane & 15;
    const int a_k_off   = (lane >> 4) * 8;
    const int b_row_off = (lane & 7) + ((lane >> 4) << 3);
    const int b_k_off   = ((lane >> 3) & 1) * 8;

    auto copy_chunk = [&](int c, int stage) {
        const uint32_t s0 = sb + stage*STG;
#pragma unroll
        for (int j = 0; j < 2; j++) {
            int row = cp_row + j*64;
            uint32_t so = (uint32_t)(row*LDA + cp_c8) * 2;
            int ga = rowBase + row;
            size_t gao = (size_t)ga*KDIM + c*32 + cp_c8;
            bool pa = (ga < M);
            cp16(s0 +         so, Ath + gao, pa);
            cp16(s0 + ARR   + so, Atl + gao, pa);
            size_t gbo = (size_t)(colBase + row)*KDIM + c*32 + cp_c8;
            cp16(s0 + 2*ARR + so, Bth + gbo, true);
            cp16(s0 + 3*ARR + so, Btl + gbo, true);
        }
        CP_COMMIT();
    };

    copy_chunk(0, 0);
    CP_WAIT0();
    __syncthreads();

    for (int c = 0; c < KDIM/32; c++) {
        const int s = c & 1;
        if (c < KDIM/32 - 1) copy_chunk(c + 1, s ^ 1);

        const uint32_t aB = sb + s*STG;
        const uint32_t bB = aB + 2*ARR;
#pragma unroll
        for (int ks = 0; ks < 2; ks++) {
            const int kb = ks * 16;
            uint32_t bh[2][4], bl[2][4];
#pragma unroll
            for (int np = 0; np < 2; np++) {
                int row = warpN*32 + np*16 + b_row_off;
                uint32_t off = (uint32_t)(row*LDA + kb + b_k_off) * 2;
                ldm_x4(bh[np], bB + off);
                ldm_x4(bl[np], bB + ARR + off);
            }
#pragma unroll
            for (int mt = 0; mt < 4; mt++) {
                uint32_t ah[4], al[4];
                int row = warpM*64 + mt*16 + a_row_off;
                uint32_t off = (uint32_t)(row*LDA + kb + a_k_off) * 2;
                ldm_x4(ah, aB + off);
                ldm_x4(al, aB + ARR + off);
#pragma unroll
                for (int nt = 0; nt < 4; nt++) {
                    const uint32_t* Bhp = &bh[nt>>1][(nt&1)*2];
                    const uint32_t* Blp = &bl[nt>>1][(nt&1)*2];
                    mma_bf16(acc[mt][nt], ah, Bhp);
                    mma_bf16(acc[mt][nt], al, Bhp);
                    mma_bf16(acc[mt][nt], ah, Blp);
                }
            }
        }
        if (c < KDIM/32 - 1) {
            CP_WAIT0();
            __syncthreads();
        }
    }

    const int g   = lane >> 2;
    const int tig = lane & 3;
#pragma unroll
    for (int mt = 0; mt < 4; mt++) {
#pragma unroll
        for (int half = 0; half < 2; half++) {
            int r = rowBase + warpM*64 + mt*16 + g + half*8;
            if (r >= M) continue;
#pragma unroll
            for (int nt = 0; nt < 4; nt++) {
                int col = colBase + warpN*32 + nt*8 + tig*2;
                float vx = acc[mt][nt][half*2+0];
                float vy = acc[mt][nt][half*2+1];
                if (bias) { vx += bias[col]; vy += bias[col+1]; }
                if (Cadd) {
                    float2 rr = *(const float2*)(Cadd + (size_t)r*Nglob + col);
                    vx += rr.x; vy += rr.y;
                }
                if (OM == 0) {
                    *(float2*)(Cf + (size_t)r*Nglob + col) = make_float2(vx, vy);
                } else {
                    __nv_bfloat16 hx = __float2bfloat16(vx);
                    __nv_bfloat16 hy = __float2bfloat16(vy);
                    __nv_bfloat162 hh = {hx, hy};
                    __nv_bfloat162 ll = {__float2bfloat16(vx - __bfloat162float(hx)),
                                         __float2bfloat16(vy - __bfloat162float(hy))};
                    *(__nv_bfloat162*)(Cbh + (size_t)r*Nglob + col) = hh;
                    *(__nv_bfloat162*)(Cbl + (size_t)r*Nglob + col) = ll;
                }
            }
        }
    }
}

// ---------------- LayerNorm -> split bf16 ----------------
__global__ void ln_kernel(const float* __restrict__ q,
                          const float* __restrict__ gamma,
                          const float* __restrict__ beta)
{
    int warp = (blockIdx.x * blockDim.x + threadIdx.x) >> 5;
    int lane = threadIdx.x & 31;
    if (warp >= NQ) return;
    const float* row = q + (size_t)warp * EMBED;
    float v[8];
    float sum = 0.f;
#pragma unroll
    for (int i = 0; i < 8; i++) { v[i] = row[lane + i*32]; sum += v[i]; }
#pragma unroll
    for (int o = 16; o; o >>= 1) sum += __shfl_xor_sync(0xffffffffu, sum, o);
    float mean = sum * (1.0f/EMBED);
    float var = 0.f;
#pragma unroll
    for (int i = 0; i < 8; i++) { float d = v[i]-mean; var += d*d; }
#pragma unroll
    for (int o = 16; o; o >>= 1) var += __shfl_xor_sync(0xffffffffu, var, o);
    var *= (1.0f/EMBED);
    float inv = rsqrtf(var + 1e-5f);
#pragma unroll
    for (int i = 0; i < 8; i++) {
        int c = lane + i*32;
        float y = (v[i]-mean)*inv*gamma[c] + beta[c];
        __nv_bfloat16 h = __float2bfloat16(y);
        g_xnh[(size_t)warp*EMBED + c] = h;
        g_xnl[(size_t)warp*EMBED + c] = __float2bfloat16(y - __bfloat162float(h));
    }
}

// ---------------- sampling: 2 queries/block, warp = (query, head-pair) ----------------
__global__ __launch_bounds__(256)
void sample_kernel(const float* __restrict__ pos,
                   const int*   __restrict__ boff,
                   const int*   __restrict__ lshapes)
{
    const int tid  = threadIdx.x;
    const int wid  = tid >> 5;
    const int lane = tid & 31;
    const int q    = blockIdx.x*2 + (wid >> 2);
    const int hb   = (wid & 3) * 2;        // head pair base
    const int li   = lane & 15;            // point/softmax index within half-warp
    const int h    = hb + (lane >> 4);

    int b = (q >= boff[1]) ? 1 : 0;

    float posy = pos[q*2+0];
    float posx = pos[q*2+1];

    int   Hi[LEVELS], Wi[LEVELS];
    float Hf[LEVELS], Wf[LEVELS];
#pragma unroll
    for (int l = 0; l < LEVELS; l++) {
        Hi[l] = lshapes[l*2+0]; Wi[l] = lshapes[l*2+1];
        Hf[l] = (float)Hi[l];   Wf[l] = (float)Wi[l];
    }

    // softmax over 16 logits, independently per half-warp (per head)
    const float* alog = g_ofat + (size_t)q*384 + 256 + h*(LEVELS*POINTS);
    float logit = alog[li];
    float mx = logit;
#pragma unroll
    for (int o = 8; o; o >>= 1) mx = fmaxf(mx, __shfl_xor_sync(0xffffffffu, mx, o));
    float e = expf(logit - mx);
    float s = e;
#pragma unroll
    for (int o = 8; o; o >>= 1) s += __shfl_xor_sync(0xffffffffu, s, o);
    float aw = e / s;

    const float* offrow = g_ofat + (size_t)q*384 + h*(LEVELS*POINTS*2);
    const __half2* vbase = (const __half2*)g_val;

    float2 acc = make_float2(0.f, 0.f);
#pragma unroll
    for (int lp = 0; lp < LEVELS*POINTS; lp++) {
        int l = lp >> 2;
        float a  = __shfl_sync(0xffffffffu, aw, (lane & 16) | lp);
        float oy = offrow[lp*2+0];
        float ox = offrow[lp*2+1];
        float hf = Hf[l], wf = Wf[l];
        float py = (posy + oy/hf)*hf - 0.5f;
        float px = (posx + ox/wf)*wf - 0.5f;
        float y0f = floorf(py), x0f = floorf(px);
        float wy = py - y0f,    wx = px - x0f;
        int y0 = (int)y0f, x0 = (int)x0f;
        int Hl = Hi[l],    Wl = Wi[l];

#pragma unroll
        for (int cc = 0; cc < 4; cc++) {
            int yi = y0 + (cc >> 1);
            int xi = x0 + (cc & 1);
            float w = ((cc >> 1) ? wy : (1.f-wy)) * ((cc & 1) ? wx : (1.f-wx));
            if (yi >= 0 && yi < Hl && xi >= 0 && xi < Wl) {
                size_t rowi = (((size_t)b*HP + yi)*WP + xi)*LEVELS + l;
                // element idx = rowi*256 + hb*32 + lane*2  -> half2 idx below
                __half2 v2 = vbase[rowi*128 + hb*16 + lane];
                float aww = a * w;
                acc.x += aww * __half2float(__low2half(v2));
                acc.y += aww * __half2float(__high2half(v2));
            }
        }
    }
    size_t cbase = (size_t)q*EMBED + hb*32 + lane*2;
    __nv_bfloat16 hx = __float2bfloat16(acc.x);
    __nv_bfloat16 hy = __float2bfloat16(acc.y);
    __nv_bfloat162 hh = {hx, hy};
    __nv_bfloat162 ll = {__float2bfloat16(acc.x - __bfloat162float(hx)),
                         __float2bfloat16(acc.y - __bfloat162float(hy))};
    *(__nv_bfloat162*)(g_smh + cbase) = hh;
    *(__nv_bfloat162*)(g_sml + cbase) = ll;
}

// ---------------- launcher ----------------
extern "C" void kernel_launch(void* const* d_in, const int* in_sizes, int n_in,
                              void* d_out, int out_size)
{
    const float* query   = (const float*)d_in[0];
    const float* qpos    = (const float*)d_in[1];
    const int*   qboff   = (const int*)  d_in[2];
    const float* fmaps   = (const float*)d_in[3];
    const int*   lshapes = (const int*)  d_in[4];
    const float* gamma   = (const float*)d_in[5];
    const float* beta    = (const float*)d_in[6];
    const float* W_q     = (const float*)d_in[7];
    const float* W_off   = (const float*)d_in[8];
    const float* b_off   = (const float*)d_in[9];
    const float* W_attn  = (const float*)d_in[10];
    const float* b_attn  = (const float*)d_in[11];
    const float* W_val   = (const float*)d_in[12];
    const float* b_val   = (const float*)d_in[13];
    const float* W_out   = (const float*)d_in[14];
    float* out = (float*)d_out;

    __nv_bfloat16 *xnh, *xnl, *xqh, *xql, *smh, *sml, *wth, *wtl;
    float *ofat, *bofat;
    __half *val, *wv16;
    cudaGetSymbolAddress((void**)&xnh,  g_xnh);
    cudaGetSymbolAddress((void**)&xnl,  g_xnl);
    cudaGetSymbolAddress((void**)&xqh,  g_xqh);
    cudaGetSymbolAddress((void**)&xql,  g_xql);
    cudaGetSymbolAddress((void**)&ofat, g_ofat);
    cudaGetSymbolAddress((void**)&val,  g_val);
    cudaGetSymbolAddress((void**)&smh,  g_smh);
    cudaGetSymbolAddress((void**)&sml,  g_sml);
    cudaGetSymbolAddress((void**)&wth,  g_wth);
    cudaGetSymbolAddress((void**)&wtl,  g_wtl);
    cudaGetSymbolAddress((void**)&wv16, g_wv16);
    cudaGetSymbolAddress((void**)&bofat, g_bofat);

    __nv_bfloat16 *wq_h   = wth,          *wq_l   = wtl;
    __nv_bfloat16 *wof_h  = wth + 65536,  *wof_l  = wtl + 65536;
    __nv_bfloat16 *wout_h = wth + 163840, *wout_l = wtl + 163840;

    const int SMEM  = 2*STG;   // 81920 for mma_gemm
    const int SMEMV = 63488;   // for val_gemm
    cudaFuncSetAttribute(mma_gemm<0>, cudaFuncAttributeMaxDynamicSharedMemorySize, SMEM);
    cudaFuncSetAttribute(mma_gemm<2>, cudaFuncAttributeMaxDynamicSharedMemorySize, SMEM);
    cudaFuncSetAttribute(val_gemm,    cudaFuncAttributeMaxDynamicSharedMemorySize, SMEMV);

    dim3 tblk(32, 8);
    const int MQT = (NQ + 127) / 128;  // 157

    // setup
    transpose_f16<<<dim3(8, 8), tblk>>>(W_val, wv16);
    ln_kernel<<<(NQ*32 + 255)/256, 256>>>(query, gamma, beta);
    bias_concat<<<2, 192>>>(b_off, b_attn);
    transpose_split<<<dim3(8, 8), tblk>>>(W_q, wq_h, wq_l, 256);
    transpose_split<<<dim3(8, 8), tblk>>>(W_off, wof_h, wof_l, 256);
    // value projection (dominant)
    val_gemm<<<dim3(2, NVAL/128), 256, SMEMV>>>(fmaps, wv16, b_val, val);
    transpose_split<<<dim3(4, 8), tblk>>>(W_attn, wof_h + 256*256, wof_l + 256*256, 128);
    transpose_split<<<dim3(8, 8), tblk>>>(W_out, wout_h, wout_l, 256);
    // xq = xn @ W_q -> split bf16
    mma_gemm<2><<<dim3(2, MQT), 256, SMEM>>>(xnh, xnl, wq_h, wq_l, nullptr, nullptr,
                                             nullptr, xqh, xql, NQ, 256);
    // [off|attn] = xq @ [W_off|W_attn] + bias -> fp32
    mma_gemm<0><<<dim3(3, MQT), 256, SMEM>>>(xqh, xql, wof_h, wof_l, bofat, nullptr,
                                             ofat, nullptr, nullptr, NQ, 384);
    // sampling
    sample_kernel<<<NQ/2, 256>>>(qpos, qboff, lshapes);
    // out = samp @ W_out + residual
    mma_gemm<0><<<dim3(2, MQT), 256, SMEM>>>(smh, sml, wout_h, wout_l, nullptr, query,
                                             out, nullptr, nullptr, NQ, 256);
}